// round 16
// baseline (speedup 1.0000x reference)
#include <cuda_runtime.h>
#include <cuda_fp16.h>
#include <cstdint>

#define K_DIM 1024
#define N_DIM 1024
#define M_DIM 65536
#define BM 128
#define BN 256
#define BK 64
#define KSTAGES (K_DIM / BK)        // 16
#define PIPE 4
#define THREADS 384                  // 8 consumer + 2 producer + 2 converter warps
#define CONS_THREADS 256
#define GRID 148                     // MUST equal panel-assignment modulus; <= SM count
#define NTILES ((M_DIM / BM) * (N_DIM / BN))   // 2048
#define NPANELS (M_DIM / BM)         // 512
#define PITCH 144                    // 128B data + 16B pad (conflict-free ldmatrix)
#define A_OFF 0
#define A_BYTES (BM * PITCH)         // 18432
#define B_OFF A_BYTES
#define B_BYTES (BN * PITCH)         // 36864
#define STAGE_BYTES (A_BYTES + B_BYTES)   // 55296
#define MBAR_OFF (PIPE * STAGE_BYTES)     // 221184
#define SMEM_TOTAL (MBAR_OFF + 128)

// ---- device-global scratch (allocation-free) ----
__device__ float g_partial[1024];
__device__ float g_scale;
__device__ int   g_flag[NPANELS];
__device__ __align__(256) __half g_wq[N_DIM * K_DIM];         // ternary W, fp16
__device__ __align__(256) __half g_xh[(size_t)M_DIM * K_DIM]; // X in fp16

__device__ __forceinline__ uint32_t smem_u32(const void* p) {
    uint32_t a;
    asm("{ .reg .u64 t; cvta.to.shared.u64 t, %1; cvt.u32.u64 %0, t; }"
        : "=r"(a) : "l"(p));
    return a;
}
__device__ __forceinline__ void cp16(uint32_t dst, const void* src) {
    asm volatile("cp.async.cg.shared.global [%0], [%1], 16;" :: "r"(dst), "l"(src));
}
__device__ __forceinline__ void mbar_init(uint32_t bar, uint32_t cnt) {
    asm volatile("mbarrier.init.shared.b64 [%0], %1;" :: "r"(bar), "r"(cnt) : "memory");
}
__device__ __forceinline__ void mbar_arrive(uint32_t bar) {
    asm volatile("mbarrier.arrive.release.cta.shared.b64 _, [%0];" :: "r"(bar) : "memory");
}
__device__ __forceinline__ void cp_arrive_noinc(uint32_t bar) {
    asm volatile("cp.async.mbarrier.arrive.noinc.shared.b64 [%0];" :: "r"(bar) : "memory");
}
__device__ __forceinline__ void wait_parity(uint32_t bar, uint32_t phase) {
    asm volatile(
        "{\n\t.reg .pred P;\n"
        "W_%=:\n\t"
        "mbarrier.try_wait.parity.acquire.cta.shared::cta.b64 P, [%0], %1, 0x989680;\n\t"
        "@P bra.uni D_%=;\n\t"
        "bra.uni W_%=;\n\t"
        "D_%=:\n\t}"
        :: "r"(bar), "r"(phase) : "memory");
}
__device__ __forceinline__ void ldsm_x4(uint32_t* r, uint32_t addr) {
    asm volatile("ldmatrix.sync.aligned.m8n8.x4.shared.b16 {%0,%1,%2,%3}, [%4];"
                 : "=r"(r[0]), "=r"(r[1]), "=r"(r[2]), "=r"(r[3]) : "r"(addr));
}
__device__ __forceinline__ void mma16816(float* c, const uint32_t* a, uint32_t b0, uint32_t b1) {
    asm volatile(
        "mma.sync.aligned.m16n8k16.row.col.f32.f16.f16.f32 "
        "{%0,%1,%2,%3}, {%4,%5,%6,%7}, {%8,%9}, {%0,%1,%2,%3};"
        : "+f"(c[0]), "+f"(c[1]), "+f"(c[2]), "+f"(c[3])
        : "r"(a[0]), "r"(a[1]), "r"(a[2]), "r"(a[3]), "r"(b0), "r"(b1));
}
__device__ __forceinline__ void stg_cs_64(float* p, float2 v) {
    asm volatile("st.global.cs.v2.f32 [%0], {%1, %2};" :: "l"(p), "f"(v.x), "f"(v.y) : "memory");
}
__device__ __forceinline__ int flag_ld(const int* f) {
    int v;
    asm volatile("ld.acquire.gpu.global.b32 %0, [%1];" : "=r"(v) : "l"(f) : "memory");
    return v;
}
__device__ __forceinline__ uint2 cvt_f4(float4 v) {
    __half2 h0 = __floats2half2_rn(v.x, v.y);
    __half2 h1 = __floats2half2_rn(v.z, v.w);
    uint2 u;
    u.x = *reinterpret_cast<uint32_t*>(&h0);
    u.y = *reinterpret_cast<uint32_t*>(&h1);
    return u;
}

// ============================ pre-kernels ============================

__global__ void k_absmean(const float* __restrict__ w) {
    __shared__ float red[256];
    int t = threadIdx.x;
    if (blockIdx.x < 2) g_flag[blockIdx.x * 256 + t] = 0;   // clear panel flags
    float4 v = *(const float4*)(w + (size_t)blockIdx.x * 1024 + t * 4);
    red[t] = fabsf(v.x) + fabsf(v.y) + fabsf(v.z) + fabsf(v.w);
    __syncthreads();
    for (int o = 128; o > 0; o >>= 1) {
        if (t < o) red[t] += red[t + o];
        __syncthreads();
    }
    if (t == 0) g_partial[blockIdx.x] = red[0];
}

__global__ void k_scale() {
    __shared__ float red[256];
    int t = threadIdx.x;
    red[t] = g_partial[t] + g_partial[t + 256] + g_partial[t + 512] + g_partial[t + 768];
    __syncthreads();
    for (int o = 128; o > 0; o >>= 1) {
        if (t < o) red[t] += red[t + o];
        __syncthreads();
    }
    if (t == 0) g_scale = fmaxf(red[0] / 1048576.0f, 1e-5f);
}

__global__ void k_quant(const float* __restrict__ w) {
    int i = (blockIdx.x * 256 + threadIdx.x) * 4;
    float s = g_scale;
    float4 v = *(const float4*)(w + i);
    float q0 = fminf(fmaxf(rintf(v.x / s), -1.0f), 1.0f);
    float q1 = fminf(fmaxf(rintf(v.y / s), -1.0f), 1.0f);
    float q2 = fminf(fmaxf(rintf(v.z / s), -1.0f), 1.0f);
    float q3 = fminf(fmaxf(rintf(v.w / s), -1.0f), 1.0f);
    __half2 h0 = __floats2half2_rn(q0, q1);
    __half2 h1 = __floats2half2_rn(q2, q3);
    uint2 u;
    u.x = *reinterpret_cast<uint32_t*>(&h0);
    u.y = *reinterpret_cast<uint32_t*>(&h1);
    *(uint2*)(g_wq + i) = u;
}

// ====== GEMM: persistent, warp-specialized + converter warps, BK64/PIPE4 =====

__global__ void __launch_bounds__(THREADS, 1)
bitlinear_gemm(const float* __restrict__ x, float* __restrict__ out) {
    extern __shared__ __align__(128) char smem[];
    uint32_t sb = smem_u32(smem);
    int tid = threadIdx.x, lane = tid & 31, wid = tid >> 5;
    int bid = blockIdx.x;

    uint32_t full0  = sb + MBAR_OFF;
    uint32_t empty0 = sb + MBAR_OFF + PIPE * 8;
    if (tid == 0) {
        #pragma unroll
        for (int i = 0; i < PIPE; i++) {
            mbar_init(full0 + i * 8, 64);      // 64 producer threads (noinc)
            mbar_init(empty0 + i * 8, 256);    // 256 consumer threads
        }
    }
    __syncthreads();

    const float4* x4 = (const float4*)x;
    uint2* xh2 = (uint2*)g_xh;

    if (wid >= 10) {
        // ===== CONVERTER (2 warps, 64 threads): lazy panels, deadline order ===
        int ct = tid - 320;                      // 0..63
        int pstart = (bid < 37) ? bid + GRID : bid;
        #pragma unroll 1
        for (int p = pstart; p < NPANELS; p += GRID) {
            size_t base = (size_t)p * 32768;     // float4 index of panel
            #pragma unroll 1
            for (int it = 0; it < 32; it++) {
                size_t f = base + (size_t)it * 1024 + ct;
                float4 v[16];
                #pragma unroll
                for (int j = 0; j < 16; j++) v[j] = x4[f + j * 64];
                #pragma unroll
                for (int j = 0; j < 16; j++) xh2[f + j * 64] = cvt_f4(v[j]);
            }
            __threadfence();
            asm volatile("bar.sync 3, 64;" ::: "memory");
            if (ct == 0) atomicAdd(&g_flag[p], 4);
        }
    } else if (wid >= 8) {
        // ===== PRODUCER (2 warps, 64 threads): pure cp.async (R10-exact) ======
        int ptid = tid - CONS_THREADS;          // 0..63
        int prow = ptid >> 3, pcol = ptid & 7;  // 8 rows x 8 col16 per pass
        uint32_t adst = sb + A_OFF + prow * PITCH + pcol * 16;
        uint32_t bdst = sb + B_OFF + prow * PITCH + pcol * 16;

        int pb = 0, pph = 1;
        #pragma unroll 1
        for (int t = bid; t < NTILES; t += GRID) {
            int m0p = t >> 2;
            int n0 = (t & 3) * BN;
            // gate on converted A panel (with backoff)
            while (flag_ld(&g_flag[m0p]) < 4) __nanosleep(64);
            const __half* abase = g_xh + (size_t)(m0p * BM + prow) * K_DIM + pcol * 8;
            const __half* bbase = g_wq + (size_t)(n0 + prow) * K_DIM + pcol * 8;
            #pragma unroll 1
            for (int s = 0; s < KSTAGES; s++) {
                wait_parity(empty0 + pb * 8, pph);
                uint32_t ab = pb * STAGE_BYTES;
                int k0 = s * BK;
                #pragma unroll
                for (int i = 0; i < 16; i++)      // A: 128 rows
                    cp16(adst + ab + i * 8 * PITCH, abase + (size_t)i * 8 * K_DIM + k0);
                #pragma unroll
                for (int i = 0; i < 32; i++)      // B: 256 rows
                    cp16(bdst + ab + i * 8 * PITCH, bbase + (size_t)i * 8 * K_DIM + k0);
                cp_arrive_noinc(full0 + pb * 8);
                if (++pb == PIPE) { pb = 0; pph ^= 1; }
            }
        }
    } else {
        // ===== CONSUMER (8 warps): upfront quarter-panel convert, then R10 ====
        {
            // convert quarter (bid&3) of panel (bid>>2): 8192 float4, 256 thr
            int q = bid >> 2, r = bid & 3;
            size_t base = (size_t)q * 32768 + (size_t)r * 8192;
            #pragma unroll
            for (int it = 0; it < 2; it++) {
                size_t f = base + (size_t)it * 4096 + tid;
                float4 v[16];
                #pragma unroll
                for (int j = 0; j < 16; j++) v[j] = x4[f + j * 256];
                #pragma unroll
                for (int j = 0; j < 16; j++) xh2[f + j * 256] = cvt_f4(v[j]);
            }
            __threadfence();
            asm volatile("bar.sync 2, 256;" ::: "memory");
            if (tid == 0) atomicAdd(&g_flag[q], 1);
        }

        int wm = wid & 1, wn = wid >> 1;         // 2 x 4 grid, 64x64 warp tiles
        uint32_t a_ld[4], b_ld[4];
        #pragma unroll
        for (int mt = 0; mt < 4; mt++)
            a_ld[mt] = sb + A_OFF + (wm * 64 + mt * 16 + (lane & 15)) * PITCH
                     + (lane >> 4) * 16;
        #pragma unroll
        for (int np = 0; np < 4; np++)
            b_ld[np] = sb + B_OFF
                     + (wn * 64 + np * 16 + (lane & 7) + ((lane >> 4) & 1) * 8) * PITCH
                     + ((lane >> 3) & 1) * 16;

        float acc[4][8][4];
        #pragma unroll
        for (int i = 0; i < 4; i++)
            #pragma unroll
            for (int j = 0; j < 8; j++)
                #pragma unroll
                for (int k = 0; k < 4; k++) acc[i][j][k] = 0.0f;

        float sc = g_scale;
        int cb = 0, cph = 0;
        #pragma unroll 1
        for (int t = bid; t < NTILES; t += GRID) {
            #pragma unroll 1
            for (int s = 0; s < KSTAGES; s++) {
                wait_parity(full0 + cb * 8, cph);
                uint32_t ab = cb * STAGE_BYTES;
                #pragma unroll
                for (int ks = 0; ks < 4; ks++) {
                    uint32_t a[4][4], b[4][4];
                    #pragma unroll
                    for (int mt = 0; mt < 4; mt++)
                        ldsm_x4(a[mt], a_ld[mt] + ab + ks * 32);
                    #pragma unroll
                    for (int np = 0; np < 4; np++)
                        ldsm_x4(b[np], b_ld[np] + ab + ks * 32);
                    #pragma unroll
                    for (int np = 0; np < 4; np++) {
                        #pragma unroll
                        for (int mt = 0; mt < 4; mt++) {
                            mma16816(acc[mt][2 * np],     a[mt], b[np][0], b[np][1]);
                            mma16816(acc[mt][2 * np + 1], a[mt], b[np][2], b[np][3]);
                        }
                    }
                }
                mbar_arrive(empty0 + cb * 8);
                if (++cb == PIPE) { cb = 0; cph ^= 1; }
            }

            int m0 = (t >> 2) * BM, n0 = (t & 3) * BN;
            int row_base = m0 + wm * 64 + (lane >> 2);
            int col_base = n0 + wn * 64 + (lane & 3) * 2;
            #pragma unroll
            for (int mt = 0; mt < 4; mt++) {
                #pragma unroll
                for (int nt = 0; nt < 8; nt++) {
                    float2 v0, v1;
                    v0.x = acc[mt][nt][0] * sc; v0.y = acc[mt][nt][1] * sc;
                    v1.x = acc[mt][nt][2] * sc; v1.y = acc[mt][nt][3] * sc;
                    acc[mt][nt][0] = 0.0f; acc[mt][nt][1] = 0.0f;
                    acc[mt][nt][2] = 0.0f; acc[mt][nt][3] = 0.0f;
                    size_t r0 = (size_t)(row_base + mt * 16) * N_DIM + col_base + nt * 8;
                    size_t r1 = r0 + 8 * N_DIM;
                    stg_cs_64(out + r0, v0);
                    stg_cs_64(out + r1, v1);
                }
            }
        }
    }
}

// ============================ launch ============================

extern "C" void kernel_launch(void* const* d_in, const int* in_sizes, int n_in,
                              void* d_out, int out_size) {
    const float* x = (const float*)d_in[0];
    const float* w = (const float*)d_in[1];
    float* out = (float*)d_out;

    cudaFuncSetAttribute(bitlinear_gemm,
                         cudaFuncAttributeMaxDynamicSharedMemorySize, SMEM_TOTAL);

    k_absmean<<<1024, 256>>>(w);
    k_scale<<<1, 256>>>();
    k_quant<<<1024, 256>>>(w);

    bitlinear_gemm<<<GRID, THREADS, SMEM_TOTAL>>>(x, out);
}

// round 17
// speedup vs baseline: 1.0245x; 1.0245x over previous
#include <cuda_runtime.h>
#include <cuda_fp16.h>
#include <cstdint>

#define K_DIM 1024
#define N_DIM 1024
#define M_DIM 65536
#define BM 128
#define BN 256
#define BK 128
#define KSTAGES (K_DIM / BK)        // 8
#define PIPE 2
#define THREADS 384                  // 8 consumer + 2 producer + 2 converter warps
#define CONS_THREADS 256
#define GRID 148                     // panel-assignment modulus; <= SM count
#define NTILES ((M_DIM / BM) * (N_DIM / BN))   // 2048
#define NPANELS (M_DIM / BM)         // 512
#define PITCH 272                    // 256B data + 16B pad (row step == 16 mod 128)
#define A_OFF 0
#define A_BYTES (BM * PITCH)         // 34816
#define B_OFF A_BYTES
#define B_BYTES (BN * PITCH)         // 69632
#define STAGE_BYTES (A_BYTES + B_BYTES)   // 104448
#define MBAR_OFF (PIPE * STAGE_BYTES)     // 208896
#define PROG_OFF (MBAR_OFF + 64)
#define SMEM_TOTAL (MBAR_OFF + 128)

// ---- device-global scratch (allocation-free) ----
__device__ float g_partial[1024];
__device__ float g_scale;
__device__ int   g_flag[NPANELS];
__device__ __align__(256) __half g_wq[N_DIM * K_DIM];         // ternary W, fp16
__device__ __align__(256) __half g_xh[(size_t)M_DIM * K_DIM]; // X in fp16

__device__ __forceinline__ uint32_t smem_u32(const void* p) {
    uint32_t a;
    asm("{ .reg .u64 t; cvta.to.shared.u64 t, %1; cvt.u32.u64 %0, t; }"
        : "=r"(a) : "l"(p));
    return a;
}
__device__ __forceinline__ void cp16(uint32_t dst, const void* src) {
    asm volatile("cp.async.cg.shared.global [%0], [%1], 16;" :: "r"(dst), "l"(src));
}
__device__ __forceinline__ void mbar_init(uint32_t bar, uint32_t cnt) {
    asm volatile("mbarrier.init.shared.b64 [%0], %1;" :: "r"(bar), "r"(cnt) : "memory");
}
__device__ __forceinline__ void mbar_arrive(uint32_t bar) {
    asm volatile("mbarrier.arrive.release.cta.shared.b64 _, [%0];" :: "r"(bar) : "memory");
}
__device__ __forceinline__ void cp_arrive_noinc(uint32_t bar) {
    asm volatile("cp.async.mbarrier.arrive.noinc.shared.b64 [%0];" :: "r"(bar) : "memory");
}
__device__ __forceinline__ void wait_parity(uint32_t bar, uint32_t phase) {
    asm volatile(
        "{\n\t.reg .pred P;\n"
        "W_%=:\n\t"
        "mbarrier.try_wait.parity.acquire.cta.shared::cta.b64 P, [%0], %1, 0x989680;\n\t"
        "@P bra.uni D_%=;\n\t"
        "bra.uni W_%=;\n\t"
        "D_%=:\n\t}"
        :: "r"(bar), "r"(phase) : "memory");
}
__device__ __forceinline__ void ldsm_x4(uint32_t* r, uint32_t addr) {
    asm volatile("ldmatrix.sync.aligned.m8n8.x4.shared.b16 {%0,%1,%2,%3}, [%4];"
                 : "=r"(r[0]), "=r"(r[1]), "=r"(r[2]), "=r"(r[3]) : "r"(addr));
}
__device__ __forceinline__ void mma16816(float* c, const uint32_t* a, uint32_t b0, uint32_t b1) {
    asm volatile(
        "mma.sync.aligned.m16n8k16.row.col.f32.f16.f16.f32 "
        "{%0,%1,%2,%3}, {%4,%5,%6,%7}, {%8,%9}, {%0,%1,%2,%3};"
        : "+f"(c[0]), "+f"(c[1]), "+f"(c[2]), "+f"(c[3])
        : "r"(a[0]), "r"(a[1]), "r"(a[2]), "r"(a[3]), "r"(b0), "r"(b1));
}
__device__ __forceinline__ void stg_cs_64(float* p, float2 v) {
    asm volatile("st.global.cs.v2.f32 [%0], {%1, %2};" :: "l"(p), "f"(v.x), "f"(v.y) : "memory");
}
__device__ __forceinline__ int flag_ld(const int* f) {
    int v;
    asm volatile("ld.acquire.gpu.global.b32 %0, [%1];" : "=r"(v) : "l"(f) : "memory");
    return v;
}
__device__ __forceinline__ void prog_st(uint32_t addr, int v) {
    asm volatile("st.volatile.shared.b32 [%0], %1;" :: "r"(addr), "r"(v) : "memory");
}
__device__ __forceinline__ int prog_ld(uint32_t addr) {
    int v;
    asm volatile("ld.volatile.shared.b32 %0, [%1];" : "=r"(v) : "r"(addr) : "memory");
    return v;
}
__device__ __forceinline__ uint2 cvt_f4(float4 v) {
    __half2 h0 = __floats2half2_rn(v.x, v.y);
    __half2 h1 = __floats2half2_rn(v.z, v.w);
    uint2 u;
    u.x = *reinterpret_cast<uint32_t*>(&h0);
    u.y = *reinterpret_cast<uint32_t*>(&h1);
    return u;
}

// ============================ pre-kernels ============================

__global__ void k_absmean(const float* __restrict__ w) {
    __shared__ float red[256];
    int t = threadIdx.x;
    if (blockIdx.x < 2) g_flag[blockIdx.x * 256 + t] = 0;   // clear panel flags
    float4 v = *(const float4*)(w + (size_t)blockIdx.x * 1024 + t * 4);
    red[t] = fabsf(v.x) + fabsf(v.y) + fabsf(v.z) + fabsf(v.w);
    __syncthreads();
    for (int o = 128; o > 0; o >>= 1) {
        if (t < o) red[t] += red[t + o];
        __syncthreads();
    }
    if (t == 0) g_partial[blockIdx.x] = red[0];
}

__global__ void k_scale() {
    __shared__ float red[256];
    int t = threadIdx.x;
    red[t] = g_partial[t] + g_partial[t + 256] + g_partial[t + 512] + g_partial[t + 768];
    __syncthreads();
    for (int o = 128; o > 0; o >>= 1) {
        if (t < o) red[t] += red[t + o];
        __syncthreads();
    }
    if (t == 0) g_scale = fmaxf(red[0] / 1048576.0f, 1e-5f);
}

__global__ void k_quant(const float* __restrict__ w) {
    int i = (blockIdx.x * 256 + threadIdx.x) * 4;
    float s = g_scale;
    float4 v = *(const float4*)(w + i);
    float q0 = fminf(fmaxf(rintf(v.x / s), -1.0f), 1.0f);
    float q1 = fminf(fmaxf(rintf(v.y / s), -1.0f), 1.0f);
    float q2 = fminf(fmaxf(rintf(v.z / s), -1.0f), 1.0f);
    float q3 = fminf(fmaxf(rintf(v.w / s), -1.0f), 1.0f);
    __half2 h0 = __floats2half2_rn(q0, q1);
    __half2 h1 = __floats2half2_rn(q2, q3);
    uint2 u;
    u.x = *reinterpret_cast<uint32_t*>(&h0);
    u.y = *reinterpret_cast<uint32_t*>(&h1);
    *(uint2*)(g_wq + i) = u;
}

// ====== GEMM: persistent, warp-specialized + paced converter warps ===========

__global__ void __launch_bounds__(THREADS, 1)
bitlinear_gemm(const float* __restrict__ x, float* __restrict__ out) {
    extern __shared__ __align__(128) char smem[];
    uint32_t sb = smem_u32(smem);
    int tid = threadIdx.x, lane = tid & 31, wid = tid >> 5;
    int bid = blockIdx.x;
    uint32_t prog = sb + PROG_OFF;

    uint32_t full0  = sb + MBAR_OFF;
    uint32_t empty0 = sb + MBAR_OFF + PIPE * 8;
    if (tid == 0) {
        #pragma unroll
        for (int i = 0; i < PIPE; i++) {
            mbar_init(full0 + i * 8, 64);      // 64 producer threads (noinc)
            mbar_init(empty0 + i * 8, 256);    // 256 consumer threads
        }
        prog_st(prog, 0);
    }
    __syncthreads();

    const float4* x4 = (const float4*)x;
    uint2* xh2 = (uint2*)g_xh;

    if (wid >= 10) {
        // ===== CONVERTER (2 warps, 64 threads): paced lazy panel conversion ===
        int ct = tid - 320;                      // 0..63
        int pstart = (bid < 37) ? bid + GRID : bid;
        #pragma unroll 1
        for (int p = pstart; p < NPANELS; p += GRID) {
            // pace: panel p is first consumed at step k_need; start 2 tiles early
            int k_need = (4 * p - bid) / GRID;
            int gate = k_need - 2;
            while (prog_ld(prog) < gate) __nanosleep(256);

            size_t base = (size_t)p * 32768;     // float4 index of panel
            #pragma unroll 1
            for (int it = 0; it < 32; it++) {
                size_t f = base + (size_t)it * 1024 + ct;
                float4 v[16];
                #pragma unroll
                for (int j = 0; j < 16; j++) v[j] = x4[f + j * 64];
                #pragma unroll
                for (int j = 0; j < 16; j++) xh2[f + j * 64] = cvt_f4(v[j]);
            }
            __threadfence();
            asm volatile("bar.sync 3, 64;" ::: "memory");
            if (ct == 0) atomicAdd(&g_flag[p], 4);
        }
    } else if (wid >= 8) {
        // ===== PRODUCER (2 warps, 64 threads): pure cp.async (R15-exact) ======
        int ptid = tid - CONS_THREADS;          // 0..63
        int prow = ptid >> 3, pcol = ptid & 7;
        uint32_t adst = sb + A_OFF + prow * PITCH + pcol * 16;
        uint32_t bdst = sb + B_OFF + prow * PITCH + pcol * 16;

        int pb = 0, pph = 1, k = 0;
        #pragma unroll 1
        for (int t = bid; t < NTILES; t += GRID, k++) {
            int m0p = t >> 2;
            int n0 = (t & 3) * BN;
            if (ptid == 0) prog_st(prog, k);     // publish progress for pacing
            while (flag_ld(&g_flag[m0p]) < 4) __nanosleep(64);
            const __half* abase = g_xh + (size_t)(m0p * BM + prow) * K_DIM + pcol * 8;
            const __half* bbase = g_wq + (size_t)(n0 + prow) * K_DIM + pcol * 8;
            #pragma unroll 1
            for (int s = 0; s < KSTAGES; s++) {
                wait_parity(empty0 + pb * 8, pph);
                uint32_t ab = pb * STAGE_BYTES;
                int k0 = s * BK;
                #pragma unroll
                for (int i = 0; i < 16; i++) {
                    int ro = i * 8;
                    cp16(adst + ab + ro * PITCH,       abase + (size_t)ro * K_DIM + k0);
                    cp16(adst + ab + ro * PITCH + 128, abase + (size_t)ro * K_DIM + k0 + 64);
                }
                #pragma unroll
                for (int i = 0; i < 32; i++) {
                    int ro = i * 8;
                    cp16(bdst + ab + ro * PITCH,       bbase + (size_t)ro * K_DIM + k0);
                    cp16(bdst + ab + ro * PITCH + 128, bbase + (size_t)ro * K_DIM + k0 + 64);
                }
                cp_arrive_noinc(full0 + pb * 8);
                if (++pb == PIPE) { pb = 0; pph ^= 1; }
            }
        }
    } else {
        // ===== CONSUMER (8 warps): upfront quarter-panel convert, then R15 ====
        {
            int q = bid >> 2, r = bid & 3;
            size_t base = (size_t)q * 32768 + (size_t)r * 8192;
            #pragma unroll
            for (int it = 0; it < 2; it++) {
                size_t f = base + (size_t)it * 4096 + tid;
                float4 v[16];
                #pragma unroll
                for (int j = 0; j < 16; j++) v[j] = x4[f + j * 256];
                #pragma unroll
                for (int j = 0; j < 16; j++) xh2[f + j * 256] = cvt_f4(v[j]);
            }
            __threadfence();
            asm volatile("bar.sync 2, 256;" ::: "memory");
            if (tid == 0) atomicAdd(&g_flag[q], 1);
        }

        int wm = wid & 1, wn = wid >> 1;         // 2 x 4 grid, 64x64 warp tiles
        uint32_t a_ld[4], b_ld[4];
        #pragma unroll
        for (int mt = 0; mt < 4; mt++)
            a_ld[mt] = sb + A_OFF + (wm * 64 + mt * 16 + (lane & 15)) * PITCH
                     + (lane >> 4) * 16;
        #pragma unroll
        for (int np = 0; np < 4; np++)
            b_ld[np] = sb + B_OFF
                     + (wn * 64 + np * 16 + (lane & 7) + ((lane >> 4) & 1) * 8) * PITCH
                     + ((lane >> 3) & 1) * 16;

        float acc[4][8][4];
        #pragma unroll
        for (int i = 0; i < 4; i++)
            #pragma unroll
            for (int j = 0; j < 8; j++)
                #pragma unroll
                for (int k = 0; k < 4; k++) acc[i][j][k] = 0.0f;

        float sc = g_scale;
        int cb = 0, cph = 0;
        #pragma unroll 1
        for (int t = bid; t < NTILES; t += GRID) {
            #pragma unroll 1
            for (int s = 0; s < KSTAGES; s++) {
                wait_parity(full0 + cb * 8, cph);
                uint32_t ab = cb * STAGE_BYTES;
                #pragma unroll
                for (int ks = 0; ks < 8; ks++) {
                    uint32_t a[4][4], b[4][4];
                    #pragma unroll
                    for (int mt = 0; mt < 4; mt++)
                        ldsm_x4(a[mt], a_ld[mt] + ab + ks * 32);
                    #pragma unroll
                    for (int np = 0; np < 4; np++)
                        ldsm_x4(b[np], b_ld[np] + ab + ks * 32);
                    #pragma unroll
                    for (int np = 0; np < 4; np++) {
                        #pragma unroll
                        for (int mt = 0; mt < 4; mt++) {
                            mma16816(acc[mt][2 * np],     a[mt], b[np][0], b[np][1]);
                            mma16816(acc[mt][2 * np + 1], a[mt], b[np][2], b[np][3]);
                        }
                    }
                }
                mbar_arrive(empty0 + cb * 8);
                if (++cb == PIPE) { cb = 0; cph ^= 1; }
            }

            int m0 = (t >> 2) * BM, n0 = (t & 3) * BN;
            int row_base = m0 + wm * 64 + (lane >> 2);
            int col_base = n0 + wn * 64 + (lane & 3) * 2;
            #pragma unroll
            for (int mt = 0; mt < 4; mt++) {
                #pragma unroll
                for (int nt = 0; nt < 8; nt++) {
                    float2 v0, v1;
                    v0.x = acc[mt][nt][0] * sc; v0.y = acc[mt][nt][1] * sc;
                    v1.x = acc[mt][nt][2] * sc; v1.y = acc[mt][nt][3] * sc;
                    acc[mt][nt][0] = 0.0f; acc[mt][nt][1] = 0.0f;
                    acc[mt][nt][2] = 0.0f; acc[mt][nt][3] = 0.0f;
                    size_t r0 = (size_t)(row_base + mt * 16) * N_DIM + col_base + nt * 8;
                    size_t r1 = r0 + 8 * N_DIM;
                    stg_cs_64(out + r0, v0);
                    stg_cs_64(out + r1, v1);
                }
            }
        }
    }
}

// ============================ launch ============================

extern "C" void kernel_launch(void* const* d_in, const int* in_sizes, int n_in,
                              void* d_out, int out_size) {
    const float* x = (const float*)d_in[0];
    const float* w = (const float*)d_in[1];
    float* out = (float*)d_out;

    cudaFuncSetAttribute(bitlinear_gemm,
                         cudaFuncAttributeMaxDynamicSharedMemorySize, SMEM_TOTAL);

    k_absmean<<<1024, 256>>>(w);
    k_scale<<<1, 256>>>();
    k_quant<<<1024, 256>>>(w);

    bitlinear_gemm<<<GRID, THREADS, SMEM_TOTAL>>>(x, out);
}